// round 1
// baseline (speedup 1.0000x reference)
#include <cuda_runtime.h>

#define BB 32
#define SS 8192
#define DD 256
#define KSEL 1638          // max(1, int(8192*0.2))
#define NCHUNK 32
#define ROWS_PER_CHUNK 256 // SS / NCHUNK
#define ROWS_PER_WARP 32   // ROWS_PER_CHUNK / 8 warps

// Scratch (no allocations allowed): ~3 MB total
__device__ float g_w[BB * SS];                 // exp(tanh(x.W + b))
__device__ float g_Ppart[NCHUNK * BB * DD];    // per-chunk partial sum x*w (all rows)
__device__ float g_Epart[NCHUNK * BB * DD];    // per-chunk partial sum x*w (top-k rows)
__device__ float g_thr[BB];
__device__ float g_invZ[BB];

// ---------------------------------------------------------------------------
// k1: e = tanh(x.W+b), w = exp(e); store w; accumulate Ppart = sum_s x*w
// Grid: BB*NCHUNK blocks of 256 threads (8 warps, 32 rows/warp).
// ---------------------------------------------------------------------------
__global__ __launch_bounds__(256) void k1_kernel(const float* __restrict__ x,
                                                 const float* __restrict__ W,
                                                 const float* __restrict__ bias)
{
    const int blk   = blockIdx.x;
    const int b     = blk / NCHUNK;
    const int chunk = blk % NCHUNK;
    const int warp  = threadIdx.x >> 5;
    const int lane  = threadIdx.x & 31;

    // W slice for this lane: d = lane*4..+3 and 128+lane*4..+3
    float w0[4], w1[4];
#pragma unroll
    for (int j = 0; j < 4; j++) {
        w0[j] = W[lane * 4 + j];
        w1[j] = W[128 + lane * 4 + j];
    }
    const float bv = bias[0];

    float acc[8];
#pragma unroll
    for (int j = 0; j < 8; j++) acc[j] = 0.f;

    const int s0 = chunk * ROWS_PER_CHUNK + warp * ROWS_PER_WARP;
    const float4* xb = (const float4*)(x + (size_t)b * SS * DD);

#pragma unroll 4
    for (int r = 0; r < ROWS_PER_WARP; r++) {
        const int s = s0 + r;
        const float4* xr = xb + (size_t)s * (DD / 4);
        float4 v0 = xr[lane];        // d = lane*4      (coalesced 512B)
        float4 v1 = xr[32 + lane];   // d = 128+lane*4  (coalesced 512B)

        float dp = v0.x * w0[0] + v0.y * w0[1] + v0.z * w0[2] + v0.w * w0[3]
                 + v1.x * w1[0] + v1.y * w1[1] + v1.z * w1[2] + v1.w * w1[3];
#pragma unroll
        for (int off = 16; off; off >>= 1) dp += __shfl_xor_sync(0xffffffffu, dp, off);

        float wv;
        if (lane == 0) {
            float e = tanhf(dp + bv);       // accurate tanh (not .approx)
            wv = __expf(e);                 // e in [-1,1]: no stability issue
            g_w[b * SS + s] = wv;
        }
        wv = __shfl_sync(0xffffffffu, wv, 0);

        acc[0] += v0.x * wv; acc[1] += v0.y * wv; acc[2] += v0.z * wv; acc[3] += v0.w * wv;
        acc[4] += v1.x * wv; acc[5] += v1.y * wv; acc[6] += v1.z * wv; acc[7] += v1.w * wv;
    }

    // Deterministic cross-warp combine (no float atomics)
    __shared__ float sacc[8][DD];
#pragma unroll
    for (int j = 0; j < 4; j++) {
        sacc[warp][lane * 4 + j]       = acc[j];
        sacc[warp][128 + lane * 4 + j] = acc[4 + j];
    }
    __syncthreads();
    float tot = 0.f;
#pragma unroll
    for (int wp = 0; wp < 8; wp++) tot += sacc[wp][threadIdx.x];
    g_Ppart[((size_t)chunk * BB + b) * DD + threadIdx.x] = tot;
}

// ---------------------------------------------------------------------------
// k2: per batch row: Z = sum(w); exact k-th largest via bitwise binary search;
// write emphasized_a. Grid: BB blocks of 256 threads. w held in registers.
// ---------------------------------------------------------------------------
__global__ __launch_bounds__(256) void k2_kernel(float* __restrict__ out_a)
{
    const int b    = blockIdx.x;
    const int t    = threadIdx.x;
    const int warp = t >> 5;
    const int lane = t & 31;

    // Strided ownership: element idx = j*256 + t (coalesced loads/stores)
    float wreg[32];
#pragma unroll
    for (int j = 0; j < 32; j++) wreg[j] = g_w[b * SS + j * 256 + t];

    __shared__ float sredf[8];
    __shared__ float sZ;
    __shared__ int   scount[8];
    __shared__ int   stot;

    // --- Z = sum ---
    float z = 0.f;
#pragma unroll
    for (int j = 0; j < 32; j++) z += wreg[j];
#pragma unroll
    for (int off = 16; off; off >>= 1) z += __shfl_xor_sync(0xffffffffu, z, off);
    if (lane == 0) sredf[warp] = z;
    __syncthreads();
    if (t == 0) {
        float zz = 0.f;
        for (int i = 0; i < 8; i++) zz += sredf[i];
        sZ = zz;
    }
    __syncthreads();
    const float invZ = 1.f / sZ;

    // --- binary search for 1638-th largest over float bits ---
    // w = exp(tanh(.)) in [e^-1, e^1] subset (0.25, 4.0): invariants hold.
    unsigned lo = 0x3E800000u;  // 0.25f: count(>=) = 8192 >= K
    unsigned hi = 0x40800000u;  // 4.0f : count(>=) = 0    <  K
    while (hi - lo > 1u) {
        const unsigned mid = lo + ((hi - lo) >> 1);
        const float fm = __uint_as_float(mid);
        int c = 0;
#pragma unroll
        for (int j = 0; j < 32; j++) c += (wreg[j] >= fm);
#pragma unroll
        for (int off = 16; off; off >>= 1) c += __shfl_xor_sync(0xffffffffu, c, off);
        if (lane == 0) scount[warp] = c;
        __syncthreads();
        if (t == 0) {
            int cc = 0;
            for (int i = 0; i < 8; i++) cc += scount[i];
            stot = cc;
        }
        __syncthreads();
        const int tot = stot;
        __syncthreads();   // protect scount/stot before next-iter writes
        if (tot >= KSEL) lo = mid; else hi = mid;
    }
    const float thr = __uint_as_float(lo);

    if (t == 0) { g_thr[b] = thr; g_invZ[b] = invZ; }

#pragma unroll
    for (int j = 0; j < 32; j++) {
        const float wv = wreg[j];
        out_a[b * SS + j * 256 + t] = wv * invZ * ((wv >= thr) ? 1.5f : 1.0f);
    }
}

// ---------------------------------------------------------------------------
// k3: Epart = sum over top-k rows of x*w (only ~20% of rows are read)
// ---------------------------------------------------------------------------
__global__ __launch_bounds__(256) void k3_kernel(const float* __restrict__ x)
{
    const int blk   = blockIdx.x;
    const int b     = blk / NCHUNK;
    const int chunk = blk % NCHUNK;
    const int warp  = threadIdx.x >> 5;
    const int lane  = threadIdx.x & 31;

    const float thr = g_thr[b];

    float acc[8];
#pragma unroll
    for (int j = 0; j < 8; j++) acc[j] = 0.f;

    const int s0 = chunk * ROWS_PER_CHUNK + warp * ROWS_PER_WARP;
    const float4* xb = (const float4*)(x + (size_t)b * SS * DD);

    for (int r = 0; r < ROWS_PER_WARP; r++) {
        const int s = s0 + r;
        const float wv = g_w[b * SS + s];   // uniform broadcast per warp
        if (wv >= thr) {                    // warp-uniform branch
            const float4* xr = xb + (size_t)s * (DD / 4);
            float4 v0 = xr[lane];
            float4 v1 = xr[32 + lane];
            acc[0] += v0.x * wv; acc[1] += v0.y * wv; acc[2] += v0.z * wv; acc[3] += v0.w * wv;
            acc[4] += v1.x * wv; acc[5] += v1.y * wv; acc[6] += v1.z * wv; acc[7] += v1.w * wv;
        }
    }

    __shared__ float sacc[8][DD];
#pragma unroll
    for (int j = 0; j < 4; j++) {
        sacc[warp][lane * 4 + j]       = acc[j];
        sacc[warp][128 + lane * 4 + j] = acc[4 + j];
    }
    __syncthreads();
    float tot = 0.f;
#pragma unroll
    for (int wp = 0; wp < 8; wp++) tot += sacc[wp][threadIdx.x];
    g_Epart[((size_t)chunk * BB + b) * DD + threadIdx.x] = tot;
}

// ---------------------------------------------------------------------------
// k4: out_sum[b,d] = invZ * (sum_c Ppart + 0.5 * sum_c Epart)
// ---------------------------------------------------------------------------
__global__ __launch_bounds__(256) void k4_kernel(float* __restrict__ out_sum)
{
    const int b = blockIdx.x;
    const int d = threadIdx.x;
    float p = 0.f, e = 0.f;
#pragma unroll
    for (int c = 0; c < NCHUNK; c++) {
        p += g_Ppart[((size_t)c * BB + b) * DD + d];
        e += g_Epart[((size_t)c * BB + b) * DD + d];
    }
    out_sum[b * DD + d] = g_invZ[b] * (p + 0.5f * e);
}

// ---------------------------------------------------------------------------
extern "C" void kernel_launch(void* const* d_in, const int* in_sizes, int n_in,
                              void* d_out, int out_size)
{
    const float* x    = (const float*)d_in[0];
    const float* W    = (const float*)d_in[1];
    const float* bias = (const float*)d_in[2];

    float* out      = (float*)d_out;
    float* out_sum  = out;              // [BB, DD]
    float* out_a    = out + BB * DD;    // [BB, SS]

    k1_kernel<<<BB * NCHUNK, 256>>>(x, W, bias);
    k2_kernel<<<BB, 256>>>(out_a);
    k3_kernel<<<BB * NCHUNK, 256>>>(x);
    k4_kernel<<<BB, 256>>>(out_sum);
}

// round 2
// speedup vs baseline: 1.0849x; 1.0849x over previous
#include <cuda_runtime.h>

#define BB 32
#define SS 8192
#define DD 256
#define KSEL 1638          // max(1, int(8192*0.2))
#define NCHUNK 32
#define ROWS_PER_CHUNK 256 // SS / NCHUNK
#define ROWS_PER_WARP 32   // ROWS_PER_CHUNK / 8 warps

// Scratch (no allocations allowed)
__device__ float g_w[BB * SS];                 // exp(tanh(x.W + b))
__device__ float g_Ppart[NCHUNK * BB * DD];    // per-chunk partial sum x*w (all rows)
__device__ float g_Epart[NCHUNK * BB * DD];    // per-chunk partial sum x*w (top-k rows)
__device__ float g_Psum[BB * DD];              // chunk-reduced P (computed in k2)
__device__ float g_thr[BB];
__device__ float g_invZ[BB];

// ---------------------------------------------------------------------------
// k1: w = exp(tanh(x.W+b)); store w; accumulate Ppart = sum_s x*w.
// 8 warps/block, 32 rows/warp processed in groups of 4 rows with 8 lanes/row:
//   lane = rowlocal*8 + e;  lane covers d = j*32 + e*4 (+0..3), j = 0..7.
// Row reduce = 3 shfl_xor (1,2,4) instead of 5; tanh/exp on all lanes.
// ---------------------------------------------------------------------------
__global__ __launch_bounds__(256, 2) void k1_kernel(const float* __restrict__ x,
                                                    const float* __restrict__ W,
                                                    const float* __restrict__ bias)
{
    const int blk   = blockIdx.x;
    const int b     = blk / NCHUNK;
    const int chunk = blk % NCHUNK;
    const int warp  = threadIdx.x >> 5;
    const int lane  = threadIdx.x & 31;
    const int rowlocal = lane >> 3;   // 0..3
    const int e        = lane & 7;    // 0..7

    const float4* Wf4 = (const float4*)W;
    float4 wreg[8];
#pragma unroll
    for (int j = 0; j < 8; j++) wreg[j] = Wf4[j * 8 + e];
    const float bv = bias[0];

    float4 acc[8];
#pragma unroll
    for (int j = 0; j < 8; j++) acc[j] = make_float4(0.f, 0.f, 0.f, 0.f);

    const int s0 = chunk * ROWS_PER_CHUNK + warp * ROWS_PER_WARP;
    const float4* xb = (const float4*)(x + (size_t)b * SS * DD);

    for (int gi = 0; gi < 8; gi++) {
        const int srow = s0 + gi * 4 + rowlocal;
        const float4* xr = xb + (size_t)srow * (DD / 4);

        float4 v[8];
#pragma unroll
        for (int j = 0; j < 8; j++) v[j] = xr[j * 8 + e];   // d = j*32 + e*4

        float dp = 0.f;
#pragma unroll
        for (int j = 0; j < 8; j++)
            dp += v[j].x * wreg[j].x + v[j].y * wreg[j].y
                + v[j].z * wreg[j].z + v[j].w * wreg[j].w;

        // reduce across the 8 lanes of this row (stays within 8-lane group)
        dp += __shfl_xor_sync(0xffffffffu, dp, 1);
        dp += __shfl_xor_sync(0xffffffffu, dp, 2);
        dp += __shfl_xor_sync(0xffffffffu, dp, 4);

        const float wv = __expf(tanhf(dp + bv));   // e in [-1,1]: stable
        if (e == 0) g_w[b * SS + srow] = wv;

#pragma unroll
        for (int j = 0; j < 8; j++) {
            acc[j].x += v[j].x * wv; acc[j].y += v[j].y * wv;
            acc[j].z += v[j].z * wv; acc[j].w += v[j].w * wv;
        }
    }

    // reduce acc across the 4 row-groups (lanes differing in bits 3,4)
#pragma unroll
    for (int j = 0; j < 8; j++) {
        acc[j].x += __shfl_xor_sync(0xffffffffu, acc[j].x, 8);
        acc[j].y += __shfl_xor_sync(0xffffffffu, acc[j].y, 8);
        acc[j].z += __shfl_xor_sync(0xffffffffu, acc[j].z, 8);
        acc[j].w += __shfl_xor_sync(0xffffffffu, acc[j].w, 8);
        acc[j].x += __shfl_xor_sync(0xffffffffu, acc[j].x, 16);
        acc[j].y += __shfl_xor_sync(0xffffffffu, acc[j].y, 16);
        acc[j].z += __shfl_xor_sync(0xffffffffu, acc[j].z, 16);
        acc[j].w += __shfl_xor_sync(0xffffffffu, acc[j].w, 16);
    }

    __shared__ float4 sacc[8][64];   // [warp][d/4]
    if (lane < 8) {
#pragma unroll
        for (int j = 0; j < 8; j++) sacc[warp][j * 8 + e] = acc[j];
    }
    __syncthreads();

    float tot = 0.f;
    const float* sflat = (const float*)sacc;
#pragma unroll
    for (int wp = 0; wp < 8; wp++) tot += sflat[wp * DD + threadIdx.x];
    g_Ppart[((size_t)chunk * BB + b) * DD + threadIdx.x] = tot;
}

// ---------------------------------------------------------------------------
// k2: per batch row: Z = sum(w); exact k-th largest via bitwise binary search;
// write emphasized_a. Also folds the P chunk-reduction (g_Psum).
// ---------------------------------------------------------------------------
__global__ __launch_bounds__(256) void k2_kernel(float* __restrict__ out_a)
{
    const int b    = blockIdx.x;
    const int t    = threadIdx.x;
    const int warp = t >> 5;
    const int lane = t & 31;

    float wreg[32];
#pragma unroll
    for (int j = 0; j < 32; j++) wreg[j] = g_w[b * SS + j * 256 + t];

    __shared__ float sredf[8];
    __shared__ float sZ;
    __shared__ int   scount[8];
    __shared__ int   stot;

    // --- Z = sum ---
    float z = 0.f;
#pragma unroll
    for (int j = 0; j < 32; j++) z += wreg[j];
#pragma unroll
    for (int off = 16; off; off >>= 1) z += __shfl_xor_sync(0xffffffffu, z, off);
    if (lane == 0) sredf[warp] = z;
    __syncthreads();
    if (t == 0) {
        float zz = 0.f;
        for (int i = 0; i < 8; i++) zz += sredf[i];
        sZ = zz;
    }
    __syncthreads();
    const float invZ = 1.f / sZ;

    // --- P chunk-reduction folded in (overlaps with barriers below) ---
    {
        float p = 0.f;
#pragma unroll
        for (int c = 0; c < NCHUNK; c++)
            p += g_Ppart[((size_t)c * BB + b) * DD + t];
        g_Psum[b * DD + t] = p;
    }

    // --- binary search for KSEL-th largest over float bit patterns ---
    unsigned lo = 0x3E800000u;  // 0.25f: count(>=) = 8192 >= K
    unsigned hi = 0x40800000u;  // 4.0f : count(>=) = 0    <  K
    while (hi - lo > 1u) {
        const unsigned mid = lo + ((hi - lo) >> 1);
        const float fm = __uint_as_float(mid);
        int c = 0;
#pragma unroll
        for (int j = 0; j < 32; j++) c += (wreg[j] >= fm);
#pragma unroll
        for (int off = 16; off; off >>= 1) c += __shfl_xor_sync(0xffffffffu, c, off);
        if (lane == 0) scount[warp] = c;
        __syncthreads();
        if (t == 0) {
            int cc = 0;
            for (int i = 0; i < 8; i++) cc += scount[i];
            stot = cc;
        }
        __syncthreads();
        const int tot = stot;
        __syncthreads();
        if (tot >= KSEL) lo = mid; else hi = mid;
    }
    const float thr = __uint_as_float(lo);

    if (t == 0) { g_thr[b] = thr; g_invZ[b] = invZ; }

#pragma unroll
    for (int j = 0; j < 32; j++) {
        const float wv = wreg[j];
        out_a[b * SS + j * 256 + t] = wv * invZ * ((wv >= thr) ? 1.5f : 1.0f);
    }
}

// ---------------------------------------------------------------------------
// k3: Epart = sum over top-k rows of x*w (only ~20% of rows are read)
// ---------------------------------------------------------------------------
__global__ __launch_bounds__(256) void k3_kernel(const float* __restrict__ x)
{
    const int blk   = blockIdx.x;
    const int b     = blk / NCHUNK;
    const int chunk = blk % NCHUNK;
    const int warp  = threadIdx.x >> 5;
    const int lane  = threadIdx.x & 31;

    const float thr = g_thr[b];

    float acc[8];
#pragma unroll
    for (int j = 0; j < 8; j++) acc[j] = 0.f;

    const int s0 = chunk * ROWS_PER_CHUNK + warp * ROWS_PER_WARP;
    const float4* xb = (const float4*)(x + (size_t)b * SS * DD);

    for (int r = 0; r < ROWS_PER_WARP; r++) {
        const int s = s0 + r;
        const float wv = g_w[b * SS + s];   // uniform broadcast per warp
        if (wv >= thr) {                    // warp-uniform branch
            const float4* xr = xb + (size_t)s * (DD / 4);
            float4 v0 = xr[lane];
            float4 v1 = xr[32 + lane];
            acc[0] += v0.x * wv; acc[1] += v0.y * wv; acc[2] += v0.z * wv; acc[3] += v0.w * wv;
            acc[4] += v1.x * wv; acc[5] += v1.y * wv; acc[6] += v1.z * wv; acc[7] += v1.w * wv;
        }
    }

    __shared__ float sacc[8][DD];
#pragma unroll
    for (int j = 0; j < 4; j++) {
        sacc[warp][lane * 4 + j]       = acc[j];
        sacc[warp][128 + lane * 4 + j] = acc[4 + j];
    }
    __syncthreads();
    float tot = 0.f;
#pragma unroll
    for (int wp = 0; wp < 8; wp++) tot += sacc[wp][threadIdx.x];
    g_Epart[((size_t)chunk * BB + b) * DD + threadIdx.x] = tot;
}

// ---------------------------------------------------------------------------
// k4: out_sum[b,d] = invZ * (Psum + 0.5 * sum_c Epart)
// 1024 threads/block: thread (d, h); h in 0..3 sums 8 chunks; smem combine.
// ---------------------------------------------------------------------------
__global__ __launch_bounds__(1024) void k4_kernel(float* __restrict__ out_sum)
{
    const int b = blockIdx.x;
    const int t = threadIdx.x;
    const int d = t & 255;
    const int h = t >> 8;    // 0..3

    float esum = 0.f;
#pragma unroll
    for (int ci = 0; ci < 8; ci++) {
        const int c = h * 8 + ci;
        esum += g_Epart[((size_t)c * BB + b) * DD + d];
    }

    __shared__ float se[4][DD];
    se[h][d] = esum;
    __syncthreads();

    if (t < DD) {
        const float et = se[0][t] + se[1][t] + se[2][t] + se[3][t];
        out_sum[b * DD + t] = g_invZ[b] * (g_Psum[b * DD + t] + 0.5f * et);
    }
}

// ---------------------------------------------------------------------------
extern "C" void kernel_launch(void* const* d_in, const int* in_sizes, int n_in,
                              void* d_out, int out_size)
{
    const float* x    = (const float*)d_in[0];
    const float* W    = (const float*)d_in[1];
    const float* bias = (const float*)d_in[2];

    float* out      = (float*)d_out;
    float* out_sum  = out;              // [BB, DD]
    float* out_a    = out + BB * DD;    // [BB, SS]

    k1_kernel<<<BB * NCHUNK, 256>>>(x, W, bias);
    k2_kernel<<<BB, 256>>>(out_a);
    k3_kernel<<<BB * NCHUNK, 256>>>(x);
    k4_kernel<<<BB, 1024>>>(out_sum);
}

// round 3
// speedup vs baseline: 1.1372x; 1.0483x over previous
#include <cuda_runtime.h>

#define BB 32
#define SS 8192
#define DD 256
#define KSEL 1638          // max(1, int(8192*0.2))
#define NCHUNK 32
#define ROWS_PER_CHUNK 256 // SS / NCHUNK
#define ROWS_PER_WARP 32   // ROWS_PER_CHUNK / 8 warps

// Scratch (no allocations allowed)
__device__ float g_w[BB * SS];                 // exp(tanh(x.W + b))
__device__ float g_Ppart[NCHUNK * BB * DD];    // per-chunk partial sum x*w (all rows)
__device__ float g_Epart[NCHUNK * BB * DD];    // per-chunk partial sum x*w (top-k rows)
__device__ float g_Psum[BB * DD];              // chunk-reduced P (computed in k2)
__device__ float g_thr[BB];
__device__ float g_invZ[BB];

// Branch-free w = exp(tanh(z)):  tanh(z) = 1 - 2/(e^{2z}+1)
// __expf + __fdividef are MUFU-based; abs error ~1e-7, no saturation branches.
__device__ __forceinline__ float exp_tanh(float z)
{
    const float ez = __expf(z + z);
    const float t  = 1.0f - __fdividef(2.0f, ez + 1.0f);
    return __expf(t);
}

// ---------------------------------------------------------------------------
// k1: w = exp(tanh(x.W+b)); store w; accumulate Ppart = sum_s x*w.
// 8 warps/block, 32 rows/warp in groups of 4 rows with 8 lanes/row:
//   lane = rowlocal*8 + e;  lane covers d = j*32 + e*4 (+0..3), j = 0..7.
// ---------------------------------------------------------------------------
__global__ __launch_bounds__(256, 2) void k1_kernel(const float* __restrict__ x,
                                                    const float* __restrict__ W,
                                                    const float* __restrict__ bias)
{
    const int blk   = blockIdx.x;
    const int b     = blk / NCHUNK;
    const int chunk = blk % NCHUNK;
    const int warp  = threadIdx.x >> 5;
    const int lane  = threadIdx.x & 31;
    const int rowlocal = lane >> 3;   // 0..3
    const int e        = lane & 7;    // 0..7

    const float4* Wf4 = (const float4*)W;
    float4 wreg[8];
#pragma unroll
    for (int j = 0; j < 8; j++) wreg[j] = Wf4[j * 8 + e];
    const float bv = bias[0];

    float4 acc[8];
#pragma unroll
    for (int j = 0; j < 8; j++) acc[j] = make_float4(0.f, 0.f, 0.f, 0.f);

    const int s0 = chunk * ROWS_PER_CHUNK + warp * ROWS_PER_WARP;
    const float4* xb = (const float4*)(x + (size_t)b * SS * DD);

    for (int gi = 0; gi < 8; gi++) {
        const int srow = s0 + gi * 4 + rowlocal;
        const float4* xr = xb + (size_t)srow * (DD / 4);

        float4 v[8];
#pragma unroll
        for (int j = 0; j < 8; j++) v[j] = xr[j * 8 + e];   // d = j*32 + e*4

        float dp = 0.f;
#pragma unroll
        for (int j = 0; j < 8; j++)
            dp += v[j].x * wreg[j].x + v[j].y * wreg[j].y
                + v[j].z * wreg[j].z + v[j].w * wreg[j].w;

        // reduce across the 8 lanes of this row
        dp += __shfl_xor_sync(0xffffffffu, dp, 1);
        dp += __shfl_xor_sync(0xffffffffu, dp, 2);
        dp += __shfl_xor_sync(0xffffffffu, dp, 4);

        const float wv = exp_tanh(dp + bv);
        if (e == 0) g_w[b * SS + srow] = wv;

#pragma unroll
        for (int j = 0; j < 8; j++) {
            acc[j].x += v[j].x * wv; acc[j].y += v[j].y * wv;
            acc[j].z += v[j].z * wv; acc[j].w += v[j].w * wv;
        }
    }

    // reduce acc across the 4 row-groups (lanes differing in bits 3,4)
#pragma unroll
    for (int j = 0; j < 8; j++) {
        acc[j].x += __shfl_xor_sync(0xffffffffu, acc[j].x, 8);
        acc[j].y += __shfl_xor_sync(0xffffffffu, acc[j].y, 8);
        acc[j].z += __shfl_xor_sync(0xffffffffu, acc[j].z, 8);
        acc[j].w += __shfl_xor_sync(0xffffffffu, acc[j].w, 8);
        acc[j].x += __shfl_xor_sync(0xffffffffu, acc[j].x, 16);
        acc[j].y += __shfl_xor_sync(0xffffffffu, acc[j].y, 16);
        acc[j].z += __shfl_xor_sync(0xffffffffu, acc[j].z, 16);
        acc[j].w += __shfl_xor_sync(0xffffffffu, acc[j].w, 16);
    }

    __shared__ float4 sacc[8][64];   // [warp][d/4]
    if (lane < 8) {
#pragma unroll
        for (int j = 0; j < 8; j++) sacc[warp][j * 8 + e] = acc[j];
    }
    __syncthreads();

    float tot = 0.f;
    const float* sflat = (const float*)sacc;
#pragma unroll
    for (int wp = 0; wp < 8; wp++) tot += sflat[wp * DD + threadIdx.x];
    g_Ppart[((size_t)chunk * BB + b) * DD + threadIdx.x] = tot;
}

// ---------------------------------------------------------------------------
// k2: per batch row: Z = sum(w); exact k-th largest via bitwise binary search
// (1 barrier per iteration, dedicated counter per iteration); write
// emphasized_a; fold the P chunk-reduction into the barrier shadow.
// ---------------------------------------------------------------------------
__global__ __launch_bounds__(256) void k2_kernel(float* __restrict__ out_a)
{
    const int b    = blockIdx.x;
    const int t    = threadIdx.x;
    const int warp = t >> 5;
    const int lane = t & 31;

    float wreg[32];
#pragma unroll
    for (int j = 0; j < 32; j++) wreg[j] = g_w[b * SS + j * 256 + t];

    __shared__ float sredf[8];
    __shared__ float sZ;
    __shared__ int   stot[32];   // one counter per binary-search iteration

    if (t < 32) stot[t] = 0;

    // --- Z = sum ---
    float z = 0.f;
#pragma unroll
    for (int j = 0; j < 32; j++) z += wreg[j];
#pragma unroll
    for (int off = 16; off; off >>= 1) z += __shfl_xor_sync(0xffffffffu, z, off);
    if (lane == 0) sredf[warp] = z;
    __syncthreads();
    if (t == 0) {
        float zz = 0.f;
        for (int i = 0; i < 8; i++) zz += sredf[i];
        sZ = zz;
    }

    // --- P chunk-reduction folded in ---
    {
        float p = 0.f;
#pragma unroll
        for (int c = 0; c < NCHUNK; c++)
            p += g_Ppart[((size_t)c * BB + b) * DD + t];
        g_Psum[b * DD + t] = p;
    }
    __syncthreads();
    const float invZ = 1.f / sZ;

    // --- binary search for KSEL-th largest over float bit patterns ---
    unsigned lo = 0x3E800000u;  // 0.25f: count(>=) = 8192 >= K
    unsigned hi = 0x40800000u;  // 4.0f : count(>=) = 0    <  K
    int it = 0;
    while (hi - lo > 1u) {
        const unsigned mid = lo + ((hi - lo) >> 1);
        const float fm = __uint_as_float(mid);
        int c = 0;
#pragma unroll
        for (int j = 0; j < 32; j++) c += (wreg[j] >= fm);
        c = __reduce_add_sync(0xffffffffu, c);
        if (lane == 0) atomicAdd(&stot[it], c);
        __syncthreads();
        const int tot = stot[it];
        if (tot >= KSEL) lo = mid; else hi = mid;
        it++;
    }
    const float thr = __uint_as_float(lo);

    if (t == 0) { g_thr[b] = thr; g_invZ[b] = invZ; }

#pragma unroll
    for (int j = 0; j < 32; j++) {
        const float wv = wreg[j];
        out_a[b * SS + j * 256 + t] = wv * invZ * ((wv >= thr) ? 1.5f : 1.0f);
    }
}

// ---------------------------------------------------------------------------
// k3: Epart = sum over top-k rows of x*w (only ~20% of rows are read)
// ---------------------------------------------------------------------------
__global__ __launch_bounds__(256) void k3_kernel(const float* __restrict__ x)
{
    const int blk   = blockIdx.x;
    const int b     = blk / NCHUNK;
    const int chunk = blk % NCHUNK;
    const int warp  = threadIdx.x >> 5;
    const int lane  = threadIdx.x & 31;

    const float thr = g_thr[b];

    float acc[8];
#pragma unroll
    for (int j = 0; j < 8; j++) acc[j] = 0.f;

    const int s0 = chunk * ROWS_PER_CHUNK + warp * ROWS_PER_WARP;
    const float4* xb = (const float4*)(x + (size_t)b * SS * DD);

    for (int r = 0; r < ROWS_PER_WARP; r++) {
        const int s = s0 + r;
        const float wv = g_w[b * SS + s];   // uniform broadcast per warp
        if (wv >= thr) {                    // warp-uniform branch
            const float4* xr = xb + (size_t)s * (DD / 4);
            float4 v0 = xr[lane];
            float4 v1 = xr[32 + lane];
            acc[0] += v0.x * wv; acc[1] += v0.y * wv; acc[2] += v0.z * wv; acc[3] += v0.w * wv;
            acc[4] += v1.x * wv; acc[5] += v1.y * wv; acc[6] += v1.z * wv; acc[7] += v1.w * wv;
        }
    }

    __shared__ float sacc[8][DD];
#pragma unroll
    for (int j = 0; j < 4; j++) {
        sacc[warp][lane * 4 + j]       = acc[j];
        sacc[warp][128 + lane * 4 + j] = acc[4 + j];
    }
    __syncthreads();
    float tot = 0.f;
#pragma unroll
    for (int wp = 0; wp < 8; wp++) tot += sacc[wp][threadIdx.x];
    g_Epart[((size_t)chunk * BB + b) * DD + threadIdx.x] = tot;
}

// ---------------------------------------------------------------------------
// k4: out_sum[b,d] = invZ * (Psum + 0.5 * sum_c Epart)
// Grid 128 blocks (b, d-quarter) x 512 threads: t -> (h = t>>6 in 0..7,
// dl = t&63); each thread sums 4 chunks; smem combine over h.
// ---------------------------------------------------------------------------
__global__ __launch_bounds__(512) void k4_kernel(float* __restrict__ out_sum)
{
    const int b  = blockIdx.x >> 2;
    const int q  = blockIdx.x & 3;
    const int t  = threadIdx.x;
    const int h  = t >> 6;          // 0..7
    const int dl = t & 63;
    const int d  = q * 64 + dl;

    float esum = 0.f;
#pragma unroll
    for (int ci = 0; ci < 4; ci++) {
        const int c = h + ci * 8;
        esum += g_Epart[((size_t)c * BB + b) * DD + d];
    }

    __shared__ float se[8][64];
    se[h][dl] = esum;
    __syncthreads();

    if (t < 64) {
        float et = 0.f;
#pragma unroll
        for (int hh = 0; hh < 8; hh++) et += se[hh][t];
        const int dd = q * 64 + t;
        out_sum[b * DD + dd] = g_invZ[b] * (g_Psum[b * DD + dd] + 0.5f * et);
    }
}

// ---------------------------------------------------------------------------
extern "C" void kernel_launch(void* const* d_in, const int* in_sizes, int n_in,
                              void* d_out, int out_size)
{
    const float* x    = (const float*)d_in[0];
    const float* W    = (const float*)d_in[1];
    const float* bias = (const float*)d_in[2];

    float* out      = (float*)d_out;
    float* out_sum  = out;              // [BB, DD]
    float* out_a    = out + BB * DD;    // [BB, SS]

    k1_kernel<<<BB * NCHUNK, 256>>>(x, W, bias);
    k2_kernel<<<BB, 256>>>(out_a);
    k3_kernel<<<BB * NCHUNK, 256>>>(x);
    k4_kernel<<<BB * 4, 512>>>(out_sum);
}